// round 15
// baseline (speedup 1.0000x reference)
#include <cuda_runtime.h>
#include <cuda_bf16.h>
#include <cstdint>

// Problem constants
#define N_TOK  8192
#define DMODEL 1024
#define NEXP   8
#define HDIM   2816
#define CAP    1280
#define SLOTS  (NEXP * CAP)          // 10240

// ---------------- device scratch (~158 MB; statics MUST stay < ~270 MB) ----
__device__ int g_slot_of_token[N_TOK];
__device__ int g_token_of_slot[SLOTS];
__device__ int g_count[NEXP];
__device__ __align__(256) __nv_bfloat16 g_xh [(size_t)SLOTS * DMODEL];
__device__ __align__(256) __nv_bfloat16 g_xl [(size_t)SLOTS * DMODEL];
__device__ __align__(256) __nv_bfloat16 g_acth[(size_t)SLOTS * HDIM];
__device__ __align__(256) __nv_bfloat16 g_actl[(size_t)SLOTS * HDIM];

__device__ __forceinline__ uint32_t smem_u32(const void* p) {
    uint32_t a;
    asm("{ .reg .u64 t; cvta.to.shared.u64 t, %1; cvt.u32.u64 %0, t; }"
        : "=r"(a) : "l"(p));
    return a;
}

#define MMA16816(d, a, b0, b1) \
    asm volatile("mma.sync.aligned.m16n8k16.row.col.f32.bf16.bf16.f32 " \
                 "{%0,%1,%2,%3}, {%4,%5,%6,%7}, {%8,%9}, {%0,%1,%2,%3};" \
                 : "+f"((d)[0]), "+f"((d)[1]), "+f"((d)[2]), "+f"((d)[3]) \
                 : "r"((a)[0]), "r"((a)[1]), "r"((a)[2]), "r"((a)[3]), \
                   "r"(b0), "r"(b1))

#define LDSM4(r, a) \
    asm volatile("ldmatrix.sync.aligned.m8n8.x4.shared.b16 {%0,%1,%2,%3}, [%4];" \
                 : "=r"((r)[0]), "=r"((r)[1]), "=r"((r)[2]), "=r"((r)[3]) : "r"(a))
#define LDSM4T(r, a) \
    asm volatile("ldmatrix.sync.aligned.m8n8.x4.trans.shared.b16 {%0,%1,%2,%3}, [%4];" \
                 : "=r"((r)[0]), "=r"((r)[1]), "=r"((r)[2]), "=r"((r)[3]) : "r"(a))

#define CP16(dst, src) \
    asm volatile("cp.async.cg.shared.global [%0], [%1], 16;" \
                 :: "r"(dst), "l"(src))
#define CP_COMMIT() asm volatile("cp.async.commit_group;" ::: "memory")
#define CP_WAIT0()  asm volatile("cp.async.wait_group 0;" ::: "memory")

// split two fp32 into packed bf16x2 hi and lo (lo = residual).
__device__ __forceinline__ void split2(float f0, float f1,
                                       uint32_t& hi, uint32_t& lo) {
    float2 f = make_float2(f0, f1);
    __nv_bfloat162 h = __float22bfloat162_rn(f);
    float2 hf = __bfloat1622float2(h);
    __nv_bfloat162 l = __float22bfloat162_rn(make_float2(f.x - hf.x, f.y - hf.y));
    hi = *(uint32_t*)&h; lo = *(uint32_t*)&l;
}

// ---------------- routing (dtype-adaptive int32/int64) ----------------------
__global__ void route_kernel(const int* __restrict__ idxw) {
    __shared__ int s_any;
    int tid = threadIdx.x;
    if (tid == 0) s_any = 0;
    for (int s = tid; s < SLOTS; s += 256) g_token_of_slot[s] = -1;
    __syncthreads();
    int local = 0;
    for (int i = 2 * tid + 1; i < N_TOK; i += 512) local |= idxw[i];
    if (local) atomicOr(&s_any, 1);
    __syncthreads();
    const int stride = s_any ? 1 : 2;
    int warp = tid >> 5, lane = tid & 31;
    if (warp < NEXP) {
        int e = warp, cnt = 0;
        for (int base = 0; base < N_TOK; base += 32) {
            int t = base + lane;
            int ei = idxw[t * stride];
            bool m = (ei == e);
            unsigned mask = __ballot_sync(0xffffffffu, m);
            if (m) {
                int pos = cnt + __popc(mask & ((1u << lane) - 1u));
                if (pos < CAP) {
                    g_slot_of_token[t] = e * CAP + pos;
                    g_token_of_slot[e * CAP + pos] = t;
                } else {
                    g_slot_of_token[t] = SLOTS;
                }
            }
            cnt += __popc(mask);
        }
        if (lane == 0) g_count[e] = (cnt < CAP) ? cnt : CAP;
    }
}

// ------- merged gather + prefill: out[t] = x[t]; kept -> split into slot ----
__global__ void gather_prefill_kernel(const float* __restrict__ x,
                                      float* __restrict__ out) {
    int t = blockIdx.x;
    int i = threadIdx.x;              // 0..255 -> float4
    float4 v = *(const float4*)(x + (size_t)t * DMODEL + i * 4);
    *(float4*)(out + (size_t)t * DMODEL + i * 4) = v;
    int slot = g_slot_of_token[t];
    if (slot < SLOTS) {
        uint32_t h01, l01, h23, l23;
        split2(v.x, v.y, h01, l01);
        split2(v.z, v.w, h23, l23);
        *(uint2*)(g_xh + (size_t)slot * DMODEL + i * 4) = make_uint2(h01, h23);
        *(uint2*)(g_xl + (size_t)slot * DMODEL + i * 4) = make_uint2(l01, l23);
    }
}

// ---------------- GEMM tiling ------------------------------------------------
#define BM 128

// gu kernel: BK=32, BN=64
#define BK 32
#define APAD 40
#define A_BUF (BM * APAD * 2)                 // 10240
#define OFF_AL (2 * A_BUF)                    // 20480
#define OFF_B0 (4 * A_BUF)                    // 40960
#define BN 64
#define BNP 72
#define B_BUF (BK * BNP * 2)                  // 4608
#define SMEM_GU (OFF_B0 + 8 * B_BUF)          // 77824

// down kernel: BK2=64, BN=64
#define BK2 64
#define DKP 72                                 // A row pitch (64 k + 8 pad)
#define A_BUF2 (BM * DKP * 2)                  // 18432
#define OFF_AL2 (2 * A_BUF2)                   // 36864
#define OFF_B2 (4 * A_BUF2)                    // 73728
#define B_BUF2 (BK2 * BNP * 2)                 // 9216
#define SMEM_DN (OFF_B2 + 4 * B_BUF2)          // 110592

// ---------------- fused gate+up GEMM ----------------------------------------
__global__ void __launch_bounds__(256, 2) gemm_gu_kernel(
        const float* __restrict__ Wg, const float* __restrict__ Wu) {
    extern __shared__ char smem[];

    const int e  = blockIdx.z;
    const int m0 = blockIdx.y * BM;
    if (m0 >= g_count[e]) return;
    const int n0 = blockIdx.x * BN;

    const size_t abase = (size_t)(e * CAP + m0) * DMODEL;
    const float* Bg = Wg + (size_t)e * DMODEL * HDIM;
    const float* Bu = Wu + (size_t)e * DMODEL * HDIM;

    const int tid  = threadIdx.x;
    const int lane = tid & 31, warp = tid >> 5;
    const int wm = warp >> 1, wn = warp & 1;
    const int fr = lane >> 2;
    const int fc = (lane & 3) * 2;

    const uint32_t sb = smem_u32(smem);
    const uint32_t aoff = (uint32_t)(wm * 32 + (lane & 15)) * (APAD * 2)
                        + (uint32_t)(lane >> 4) * 16;
    const uint32_t boff = (uint32_t)(lane & 15) * (BNP * 2)
                        + (uint32_t)(wn * 32 + (lane >> 4) * 8) * 2;

    const int ar0 = tid >> 2, ac0 = (tid & 3) * 8;
    const int ar1 = ar0 + 64;
    const int br0 = tid >> 4, bc0 = (tid & 15) * 4;
    const int br1 = br0 + 16;

    auto issueA = [&](int c, int buf) {
        const int k0 = c * BK;
        const uint32_t d0 = sb + buf * A_BUF + (uint32_t)(ar0 * APAD + ac0) * 2;
        const uint32_t d1 = sb + buf * A_BUF + (uint32_t)(ar1 * APAD + ac0) * 2;
        CP16(d0,          g_xh + abase + (size_t)ar0 * DMODEL + k0 + ac0);
        CP16(d0 + OFF_AL, g_xl + abase + (size_t)ar0 * DMODEL + k0 + ac0);
        CP16(d1,          g_xh + abase + (size_t)ar1 * DMODEL + k0 + ac0);
        CP16(d1 + OFF_AL, g_xl + abase + (size_t)ar1 * DMODEL + k0 + ac0);
        CP_COMMIT();
    };

    float4 pbg0, pbg1, pbu0, pbu1;
    auto prefetchB = [&](int c) {
        const int k0 = c * BK;
        pbg0 = *(const float4*)(Bg + (size_t)(k0 + br0) * HDIM + n0 + bc0);
        pbg1 = *(const float4*)(Bg + (size_t)(k0 + br1) * HDIM + n0 + bc0);
        pbu0 = *(const float4*)(Bu + (size_t)(k0 + br0) * HDIM + n0 + bc0);
        pbu1 = *(const float4*)(Bu + (size_t)(k0 + br1) * HDIM + n0 + bc0);
    };
    auto storeB = [&](int buf) {
        __nv_bfloat16* pgh = (__nv_bfloat16*)(smem + OFF_B0 + buf * B_BUF);
        __nv_bfloat16* pgl = (__nv_bfloat16*)(smem + OFF_B0 + 2 * B_BUF + buf * B_BUF);
        __nv_bfloat16* puh = (__nv_bfloat16*)(smem + OFF_B0 + 4 * B_BUF + buf * B_BUF);
        __nv_bfloat16* pul = (__nv_bfloat16*)(smem + OFF_B0 + 6 * B_BUF + buf * B_BUF);
        uint32_t h01, l01, h23, l23;
        split2(pbg0.x, pbg0.y, h01, l01); split2(pbg0.z, pbg0.w, h23, l23);
        *(uint2*)&pgh[br0 * BNP + bc0] = make_uint2(h01, h23);
        *(uint2*)&pgl[br0 * BNP + bc0] = make_uint2(l01, l23);
        split2(pbg1.x, pbg1.y, h01, l01); split2(pbg1.z, pbg1.w, h23, l23);
        *(uint2*)&pgh[br1 * BNP + bc0] = make_uint2(h01, h23);
        *(uint2*)&pgl[br1 * BNP + bc0] = make_uint2(l01, l23);
        split2(pbu0.x, pbu0.y, h01, l01); split2(pbu0.z, pbu0.w, h23, l23);
        *(uint2*)&puh[br0 * BNP + bc0] = make_uint2(h01, h23);
        *(uint2*)&pul[br0 * BNP + bc0] = make_uint2(l01, l23);
        split2(pbu1.x, pbu1.y, h01, l01); split2(pbu1.z, pbu1.w, h23, l23);
        *(uint2*)&puh[br1 * BNP + bc0] = make_uint2(h01, h23);
        *(uint2*)&pul[br1 * BNP + bc0] = make_uint2(l01, l23);
    };

    float accG[2][4][4], accU[2][4][4];
#pragma unroll
    for (int i = 0; i < 2; i++)
#pragma unroll
        for (int j = 0; j < 4; j++)
#pragma unroll
            for (int q = 0; q < 4; q++) { accG[i][j][q] = 0.f; accU[i][j][q] = 0.f; }

    const int kchunks = DMODEL / BK;   // 32
    prefetchB(0);
    issueA(0, 0);
    storeB(0);
    prefetchB(1);
    CP_WAIT0();
    __syncthreads();

    for (int c = 0; c < kchunks; c++) {
        const int buf = c & 1;
        if (c + 1 < kchunks) {
            issueA(c + 1, buf ^ 1);
            storeB(buf ^ 1);
            if (c + 2 < kchunks) prefetchB(c + 2);
        }

        const uint32_t uAh = sb + buf * A_BUF + aoff;
        const uint32_t uAl = uAh + OFF_AL;
        const uint32_t uBg = sb + OFF_B0 + buf * B_BUF + boff;

#pragma unroll
        for (int ks = 0; ks < 2; ks++) {
            const uint32_t ko = ks * (16 * BNP * 2);
            uint32_t ah[2][4], al[2][4];
#pragma unroll
            for (int mt = 0; mt < 2; mt++) {
                LDSM4(ah[mt], uAh + mt * (16 * APAD * 2) + ks * 32);
                LDSM4(al[mt], uAl + mt * (16 * APAD * 2) + ks * 32);
            }
            {
                uint32_t bh[4][2], bl[4][2], r[4];
#pragma unroll
                for (int ng = 0; ng < 2; ng++) {
                    LDSM4T(r, uBg + ko + ng * 32);
                    bh[2*ng][0]=r[0]; bh[2*ng][1]=r[1];
                    bh[2*ng+1][0]=r[2]; bh[2*ng+1][1]=r[3];
                    LDSM4T(r, uBg + 2 * B_BUF + ko + ng * 32);
                    bl[2*ng][0]=r[0]; bl[2*ng][1]=r[1];
                    bl[2*ng+1][0]=r[2]; bl[2*ng+1][1]=r[3];
                }
#pragma unroll
                for (int nt = 0; nt < 4; nt++)
#pragma unroll
                    for (int mt = 0; mt < 2; mt++) {
                        MMA16816(accG[mt][nt], ah[mt], bh[nt][0], bh[nt][1]);
                        MMA16816(accG[mt][nt], ah[mt], bl[nt][0], bl[nt][1]);
                        MMA16816(accG[mt][nt], al[mt], bh[nt][0], bh[nt][1]);
                    }
            }
            {
                uint32_t bh[4][2], bl[4][2], r[4];
#pragma unroll
                for (int ng = 0; ng < 2; ng++) {
                    LDSM4T(r, uBg + 4 * B_BUF + ko + ng * 32);
                    bh[2*ng][0]=r[0]; bh[2*ng][1]=r[1];
                    bh[2*ng+1][0]=r[2]; bh[2*ng+1][1]=r[3];
                    LDSM4T(r, uBg + 6 * B_BUF + ko + ng * 32);
                    bl[2*ng][0]=r[0]; bl[2*ng][1]=r[1];
                    bl[2*ng+1][0]=r[2]; bl[2*ng+1][1]=r[3];
                }
#pragma unroll
                for (int nt = 0; nt < 4; nt++)
#pragma unroll
                    for (int mt = 0; mt < 2; mt++) {
                        MMA16816(accU[mt][nt], ah[mt], bh[nt][0], bh[nt][1]);
                        MMA16816(accU[mt][nt], ah[mt], bl[nt][0], bl[nt][1]);
                        MMA16816(accU[mt][nt], al[mt], bh[nt][0], bh[nt][1]);
                    }
            }
        }
        if (c + 1 < kchunks) CP_WAIT0();
        __syncthreads();
    }

    // ---- epilogue: act = silu(g) * u -> split bf16
#pragma unroll
    for (int mt = 0; mt < 2; mt++) {
#pragma unroll
        for (int half = 0; half < 2; half++) {
            const size_t slotrow =
                (size_t)(e * CAP + m0 + wm * 32 + mt * 16 + half * 8 + fr);
#pragma unroll
            for (int nt = 0; nt < 4; nt++) {
                const int gcol = n0 + wn * 32 + nt * 8 + fc;
                float gg0 = accG[mt][nt][half * 2 + 0];
                float gg1 = accG[mt][nt][half * 2 + 1];
                float uu0 = accU[mt][nt][half * 2 + 0];
                float uu1 = accU[mt][nt][half * 2 + 1];
                float a0 = (gg0 / (1.f + __expf(-gg0))) * uu0;
                float a1 = (gg1 / (1.f + __expf(-gg1))) * uu1;
                uint32_t hi, lo;
                split2(a0, a1, hi, lo);
                *(uint32_t*)&g_acth[slotrow * HDIM + gcol] = hi;
                *(uint32_t*)&g_actl[slotrow * HDIM + gcol] = lo;
            }
        }
    }
}

// ------- down GEMM (BK2=64) + fused scatter: out[tok] = score * ACT@Wd ------
__global__ void __launch_bounds__(256, 2) gemm_down_kernel(
        const float* __restrict__ Wd, const float* __restrict__ scores,
        float* __restrict__ out) {
    extern __shared__ char smem[];
    __shared__ int   s_tok[BM];
    __shared__ float s_scr[BM];

    const int e  = blockIdx.z;
    const int m0 = blockIdx.y * BM;
    if (m0 >= g_count[e]) return;
    const int n0 = blockIdx.x * BN;

    const size_t abase = (size_t)(e * CAP + m0) * HDIM;
    const float* Bd = Wd + (size_t)e * HDIM * DMODEL;

    const int tid  = threadIdx.x;
    const int lane = tid & 31, warp = tid >> 5;
    const int wm = warp >> 1, wn = warp & 1;
    const int fr = lane >> 2;
    const int fc = (lane & 3) * 2;

    if (tid < BM) {
        int tok = g_token_of_slot[e * CAP + m0 + tid];
        s_tok[tid] = tok;
        s_scr[tid] = (tok >= 0) ? scores[tok] : 0.f;
    }

    const uint32_t sb = smem_u32(smem);
    const uint32_t aoff = (uint32_t)(wm * 32 + (lane & 15)) * (DKP * 2)
                        + (uint32_t)(lane >> 4) * 16;
    const uint32_t boff = (uint32_t)(lane & 15) * (BNP * 2)
                        + (uint32_t)(wn * 32 + (lane >> 4) * 8) * 2;

    // A: 128 rows x 64 k bf16; each thread covers 32 bf16 (64B) of a half-row
    const int ar0 = tid >> 1, ac0 = (tid & 1) * 32;
    // B: 64 k-rows x 64 n fp32 -> 16 floats/thread = 4 float4
    const int bkr = tid >> 2, bcb = (tid & 3) * 16;

    auto issueA = [&](int c, int buf) {
        const int k0 = c * BK2;
        const uint32_t d0 = sb + buf * A_BUF2 + (uint32_t)(ar0 * DKP + ac0) * 2;
        const size_t s0 = abase + (size_t)ar0 * HDIM + k0 + ac0;
        CP16(d0,                 g_acth + s0);
        CP16(d0 + 16,            g_acth + s0 + 8);
        CP16(d0 + 32,            g_acth + s0 + 16);
        CP16(d0 + 48,            g_acth + s0 + 24);
        CP16(d0 + OFF_AL2,       g_actl + s0);
        CP16(d0 + OFF_AL2 + 16,  g_actl + s0 + 8);
        CP16(d0 + OFF_AL2 + 32,  g_actl + s0 + 16);
        CP16(d0 + OFF_AL2 + 48,  g_actl + s0 + 24);
        CP_COMMIT();
    };

    float4 pb[4];
    auto prefetchB = [&](int c) {
        const int k0 = c * BK2;
#pragma unroll
        for (int j = 0; j < 4; j++)
            pb[j] = *(const float4*)(Bd + (size_t)(k0 + bkr) * DMODEL
                                     + n0 + bcb + j * 4);
    };
    auto storeB = [&](int buf) {
        __nv_bfloat16* pBh = (__nv_bfloat16*)(smem + OFF_B2 + buf * B_BUF2);
        __nv_bfloat16* pBl = (__nv_bfloat16*)(smem + OFF_B2 + 2 * B_BUF2 + buf * B_BUF2);
#pragma unroll
        for (int j = 0; j < 4; j++) {
            uint32_t h01, l01, h23, l23;
            split2(pb[j].x, pb[j].y, h01, l01);
            split2(pb[j].z, pb[j].w, h23, l23);
            *(uint2*)&pBh[bkr * BNP + bcb + j * 4] = make_uint2(h01, h23);
            *(uint2*)&pBl[bkr * BNP + bcb + j * 4] = make_uint2(l01, l23);
        }
    };

    float acc[2][4][4];
#pragma unroll
    for (int i = 0; i < 2; i++)
#pragma unroll
        for (int j = 0; j < 4; j++)
#pragma unroll
            for (int q = 0; q < 4; q++) acc[i][j][q] = 0.f;

    const int kchunks = HDIM / BK2;   // 44
    prefetchB(0);
    issueA(0, 0);
    storeB(0);
    prefetchB(1);
    CP_WAIT0();
    __syncthreads();

    for (int c = 0; c < kchunks; c++) {
        const int buf = c & 1;
        if (c + 1 < kchunks) {
            issueA(c + 1, buf ^ 1);
            storeB(buf ^ 1);
            if (c + 2 < kchunks) prefetchB(c + 2);
        }

        const uint32_t uAh = sb + buf * A_BUF2 + aoff;
        const uint32_t uAl = uAh + OFF_AL2;
        const uint32_t uBh = sb + OFF_B2 + buf * B_BUF2 + boff;
        const uint32_t uBl = uBh + 2 * B_BUF2;

#pragma unroll
        for (int ks = 0; ks < 4; ks++) {
            const uint32_t ko = ks * (16 * BNP * 2);
            uint32_t ah[2][4], al[2][4];
#pragma unroll
            for (int mt = 0; mt < 2; mt++) {
                LDSM4(ah[mt], uAh + mt * (16 * DKP * 2) + ks * 32);
                LDSM4(al[mt], uAl + mt * (16 * DKP * 2) + ks * 32);
            }
            uint32_t bh[4][2], bl[4][2], r[4];
#pragma unroll
            for (int ng = 0; ng < 2; ng++) {
                LDSM4T(r, uBh + ko + ng * 32);
                bh[2*ng][0]=r[0]; bh[2*ng][1]=r[1];
                bh[2*ng+1][0]=r[2]; bh[2*ng+1][1]=r[3];
                LDSM4T(r, uBl + ko + ng * 32);
                bl[2*ng][0]=r[0]; bl[2*ng][1]=r[1];
                bl[2*ng+1][0]=r[2]; bl[2*ng+1][1]=r[3];
            }
#pragma unroll
            for (int nt = 0; nt < 4; nt++)
#pragma unroll
                for (int mt = 0; mt < 2; mt++) {
                    MMA16816(acc[mt][nt], ah[mt], bh[nt][0], bh[nt][1]);
                    MMA16816(acc[mt][nt], ah[mt], bl[nt][0], bl[nt][1]);
                    MMA16816(acc[mt][nt], al[mt], bh[nt][0], bh[nt][1]);
                }
        }
        if (c + 1 < kchunks) CP_WAIT0();
        __syncthreads();
    }

    // ---- epilogue: out[token] = score * acc (fused scatter) ----
#pragma unroll
    for (int mt = 0; mt < 2; mt++) {
#pragma unroll
        for (int half = 0; half < 2; half++) {
            const int lrow = wm * 32 + mt * 16 + half * 8 + fr;
            const int tok = s_tok[lrow];
            if (tok < 0) continue;
            const float s = s_scr[lrow];
#pragma unroll
            for (int nt = 0; nt < 4; nt++) {
                const int gcol = n0 + wn * 32 + nt * 8 + fc;
                *(float2*)&out[(size_t)tok * DMODEL + gcol] =
                    make_float2(s * acc[mt][nt][half * 2 + 0],
                                s * acc[mt][nt][half * 2 + 1]);
            }
        }
    }
}

// -----------------------------------------------------------------------------
extern "C" void kernel_launch(void* const* d_in, const int* in_sizes, int n_in,
                              void* d_out, int out_size) {
    const float* x      = (const float*)d_in[0];
    const int*   idxw   = (const int*)d_in[1];
    const float* scores = (const float*)d_in[2];
    const float* Wg     = (const float*)d_in[3];
    const float* Wu     = (const float*)d_in[4];
    const float* Wd     = (const float*)d_in[5];
    float*       out    = (float*)d_out;

    cudaFuncSetAttribute(gemm_gu_kernel,
                         cudaFuncAttributeMaxDynamicSharedMemorySize, SMEM_GU);
    cudaFuncSetAttribute(gemm_down_kernel,
                         cudaFuncAttributeMaxDynamicSharedMemorySize, SMEM_DN);

    route_kernel<<<1, 256>>>(idxw);
    gather_prefill_kernel<<<N_TOK, 256>>>(x, out);

    gemm_gu_kernel<<<dim3(HDIM / BN, CAP / BM, NEXP), 256, SMEM_GU>>>(Wg, Wu);
    gemm_down_kernel<<<dim3(DMODEL / BN, CAP / BM, NEXP), 256, SMEM_DN>>>(
        Wd, scores, out);
}

// round 16
// speedup vs baseline: 1.4905x; 1.4905x over previous
#include <cuda_runtime.h>
#include <cuda_fp16.h>
#include <cstdint>

// Problem constants
#define N_TOK  8192
#define DMODEL 1024
#define NEXP   8
#define HDIM   2816
#define CAP    1280
#define SLOTS  (NEXP * CAP)          // 10240

// ---------------- device scratch (~158 MB; statics MUST stay < ~270 MB) ----
__device__ int g_slot_of_token[N_TOK];
__device__ int g_token_of_slot[SLOTS];
__device__ int g_count[NEXP];
__device__ __align__(256) __half g_xh [(size_t)SLOTS * DMODEL];
__device__ __align__(256) __half g_xl [(size_t)SLOTS * DMODEL];
__device__ __align__(256) __half g_acth[(size_t)SLOTS * HDIM];
__device__ __align__(256) __half g_actl[(size_t)SLOTS * HDIM];

__device__ __forceinline__ uint32_t smem_u32(const void* p) {
    uint32_t a;
    asm("{ .reg .u64 t; cvta.to.shared.u64 t, %1; cvt.u32.u64 %0, t; }"
        : "=r"(a) : "l"(p));
    return a;
}

#define MMA16816(d, a, b0, b1) \
    asm volatile("mma.sync.aligned.m16n8k16.row.col.f32.f16.f16.f32 " \
                 "{%0,%1,%2,%3}, {%4,%5,%6,%7}, {%8,%9}, {%0,%1,%2,%3};" \
                 : "+f"((d)[0]), "+f"((d)[1]), "+f"((d)[2]), "+f"((d)[3]) \
                 : "r"((a)[0]), "r"((a)[1]), "r"((a)[2]), "r"((a)[3]), \
                   "r"(b0), "r"(b1))

#define LDSM4(r, a) \
    asm volatile("ldmatrix.sync.aligned.m8n8.x4.shared.b16 {%0,%1,%2,%3}, [%4];" \
                 : "=r"((r)[0]), "=r"((r)[1]), "=r"((r)[2]), "=r"((r)[3]) : "r"(a))
#define LDSM4T(r, a) \
    asm volatile("ldmatrix.sync.aligned.m8n8.x4.trans.shared.b16 {%0,%1,%2,%3}, [%4];" \
                 : "=r"((r)[0]), "=r"((r)[1]), "=r"((r)[2]), "=r"((r)[3]) : "r"(a))

#define CP16(dst, src) \
    asm volatile("cp.async.cg.shared.global [%0], [%1], 16;" \
                 :: "r"(dst), "l"(src))
#define CP_COMMIT() asm volatile("cp.async.commit_group;" ::: "memory")
#define CP_WAIT0()  asm volatile("cp.async.wait_group 0;" ::: "memory")

// split two fp32 into packed fp16x2 hi and lo (lo = residual)
__device__ __forceinline__ void split2(float f0, float f1,
                                       uint32_t& hi, uint32_t& lo) {
    float2 f = make_float2(f0, f1);
    __half2 h = __float22half2_rn(f);
    float2 hf = __half22float2(h);
    __half2 l = __float22half2_rn(make_float2(f.x - hf.x, f.y - hf.y));
    hi = *(uint32_t*)&h; lo = *(uint32_t*)&l;
}
// round two fp32 to packed fp16x2 (single plane)
__device__ __forceinline__ uint32_t pack_h2(float f0, float f1) {
    __half2 h = __float22half2_rn(make_float2(f0, f1));
    return *(uint32_t*)&h;
}

// ---------------- routing (dtype-adaptive int32/int64) ----------------------
__global__ void route_kernel(const int* __restrict__ idxw) {
    __shared__ int s_any;
    int tid = threadIdx.x;
    if (tid == 0) s_any = 0;
    for (int s = tid; s < SLOTS; s += 256) g_token_of_slot[s] = -1;
    __syncthreads();
    int local = 0;
    for (int i = 2 * tid + 1; i < N_TOK; i += 512) local |= idxw[i];
    if (local) atomicOr(&s_any, 1);
    __syncthreads();
    const int stride = s_any ? 1 : 2;
    int warp = tid >> 5, lane = tid & 31;
    if (warp < NEXP) {
        int e = warp, cnt = 0;
        for (int base = 0; base < N_TOK; base += 32) {
            int t = base + lane;
            int ei = idxw[t * stride];
            bool m = (ei == e);
            unsigned mask = __ballot_sync(0xffffffffu, m);
            if (m) {
                int pos = cnt + __popc(mask & ((1u << lane) - 1u));
                if (pos < CAP) {
                    g_slot_of_token[t] = e * CAP + pos;
                    g_token_of_slot[e * CAP + pos] = t;
                } else {
                    g_slot_of_token[t] = SLOTS;
                }
            }
            cnt += __popc(mask);
        }
        if (lane == 0) g_count[e] = (cnt < CAP) ? cnt : CAP;
    }
}

// ------- merged gather + prefill: out[t] = x[t]; kept -> split into slot ----
__global__ void gather_prefill_kernel(const float* __restrict__ x,
                                      float* __restrict__ out) {
    int t = blockIdx.x;
    int i = threadIdx.x;              // 0..255 -> float4
    float4 v = *(const float4*)(x + (size_t)t * DMODEL + i * 4);
    *(float4*)(out + (size_t)t * DMODEL + i * 4) = v;
    int slot = g_slot_of_token[t];
    if (slot < SLOTS) {
        uint32_t h01, l01, h23, l23;
        split2(v.x, v.y, h01, l01);
        split2(v.z, v.w, h23, l23);
        *(uint2*)(g_xh + (size_t)slot * DMODEL + i * 4) = make_uint2(h01, h23);
        *(uint2*)(g_xl + (size_t)slot * DMODEL + i * 4) = make_uint2(l01, l23);
    }
}

// ---------------- GEMM tiling ------------------------------------------------
#define BM 128
#define BK 32
#define APAD 40
#define A_BUF (BM * APAD * 2)                 // 10240
#define OFF_AL (2 * A_BUF)                    // 20480
#define OFF_B0 (4 * A_BUF)                    // 40960

// gu kernel: BN=64; single-plane B (gate, up)
#define BN 64
#define BNP 72
#define B_BUF (BK * BNP * 2)                  // 4608
#define SMEM_GU (OFF_B0 + 4 * B_BUF)          // 59392

// down kernel: BN2=128; single-plane B
#define BN2 128
#define BNP2 136
#define B_BUF2 (BK * BNP2 * 2)                // 8704
#define SMEM_DN (OFF_B0 + 2 * B_BUF2)         // 58368

// ---------------- fused gate+up GEMM ----------------------------------------
__global__ void __launch_bounds__(256, 2) gemm_gu_kernel(
        const float* __restrict__ Wg, const float* __restrict__ Wu) {
    extern __shared__ char smem[];

    const int e  = blockIdx.z;
    const int m0 = blockIdx.y * BM;
    if (m0 >= g_count[e]) return;
    const int n0 = blockIdx.x * BN;

    const size_t abase = (size_t)(e * CAP + m0) * DMODEL;
    const float* Bg = Wg + (size_t)e * DMODEL * HDIM;
    const float* Bu = Wu + (size_t)e * DMODEL * HDIM;

    const int tid  = threadIdx.x;
    const int lane = tid & 31, warp = tid >> 5;
    const int wm = warp >> 1, wn = warp & 1;
    const int fr = lane >> 2;
    const int fc = (lane & 3) * 2;

    const uint32_t sb = smem_u32(smem);
    const uint32_t aoff = (uint32_t)(wm * 32 + (lane & 15)) * (APAD * 2)
                        + (uint32_t)(lane >> 4) * 16;
    const uint32_t boff = (uint32_t)(lane & 15) * (BNP * 2)
                        + (uint32_t)(wn * 32 + (lane >> 4) * 8) * 2;

    const int ar0 = tid >> 2, ac0 = (tid & 3) * 8;
    const int ar1 = ar0 + 64;
    const int br0 = tid >> 4, bc0 = (tid & 15) * 4;
    const int br1 = br0 + 16;

    auto issueA = [&](int c, int buf) {
        const int k0 = c * BK;
        const uint32_t d0 = sb + buf * A_BUF + (uint32_t)(ar0 * APAD + ac0) * 2;
        const uint32_t d1 = sb + buf * A_BUF + (uint32_t)(ar1 * APAD + ac0) * 2;
        CP16(d0,          g_xh + abase + (size_t)ar0 * DMODEL + k0 + ac0);
        CP16(d0 + OFF_AL, g_xl + abase + (size_t)ar0 * DMODEL + k0 + ac0);
        CP16(d1,          g_xh + abase + (size_t)ar1 * DMODEL + k0 + ac0);
        CP16(d1 + OFF_AL, g_xl + abase + (size_t)ar1 * DMODEL + k0 + ac0);
        CP_COMMIT();
    };

    float4 pbg0, pbg1, pbu0, pbu1;
    auto prefetchB = [&](int c) {
        const int k0 = c * BK;
        pbg0 = *(const float4*)(Bg + (size_t)(k0 + br0) * HDIM + n0 + bc0);
        pbg1 = *(const float4*)(Bg + (size_t)(k0 + br1) * HDIM + n0 + bc0);
        pbu0 = *(const float4*)(Bu + (size_t)(k0 + br0) * HDIM + n0 + bc0);
        pbu1 = *(const float4*)(Bu + (size_t)(k0 + br1) * HDIM + n0 + bc0);
    };
    auto storeB = [&](int buf) {
        __half* pg = (__half*)(smem + OFF_B0 + buf * B_BUF);
        __half* pu = (__half*)(smem + OFF_B0 + 2 * B_BUF + buf * B_BUF);
        *(uint2*)&pg[br0 * BNP + bc0] =
            make_uint2(pack_h2(pbg0.x, pbg0.y), pack_h2(pbg0.z, pbg0.w));
        *(uint2*)&pg[br1 * BNP + bc0] =
            make_uint2(pack_h2(pbg1.x, pbg1.y), pack_h2(pbg1.z, pbg1.w));
        *(uint2*)&pu[br0 * BNP + bc0] =
            make_uint2(pack_h2(pbu0.x, pbu0.y), pack_h2(pbu0.z, pbu0.w));
        *(uint2*)&pu[br1 * BNP + bc0] =
            make_uint2(pack_h2(pbu1.x, pbu1.y), pack_h2(pbu1.z, pbu1.w));
    };

    float accG[2][4][4], accU[2][4][4];
#pragma unroll
    for (int i = 0; i < 2; i++)
#pragma unroll
        for (int j = 0; j < 4; j++)
#pragma unroll
            for (int q = 0; q < 4; q++) { accG[i][j][q] = 0.f; accU[i][j][q] = 0.f; }

    const int kchunks = DMODEL / BK;   // 32
    prefetchB(0);
    issueA(0, 0);
    storeB(0);
    prefetchB(1);
    CP_WAIT0();
    __syncthreads();

    for (int c = 0; c < kchunks; c++) {
        const int buf = c & 1;
        if (c + 1 < kchunks) {
            issueA(c + 1, buf ^ 1);
            storeB(buf ^ 1);
            if (c + 2 < kchunks) prefetchB(c + 2);
        }

        const uint32_t uAh = sb + buf * A_BUF + aoff;
        const uint32_t uAl = uAh + OFF_AL;
        const uint32_t uBg = sb + OFF_B0 + buf * B_BUF + boff;
        const uint32_t uBu = uBg + 2 * B_BUF;

#pragma unroll
        for (int ks = 0; ks < 2; ks++) {
            const uint32_t ko = ks * (16 * BNP * 2);
            uint32_t ah[2][4], al[2][4];
#pragma unroll
            for (int mt = 0; mt < 2; mt++) {
                LDSM4(ah[mt], uAh + mt * (16 * APAD * 2) + ks * 32);
                LDSM4(al[mt], uAl + mt * (16 * APAD * 2) + ks * 32);
            }
            uint32_t bg[4][2], bu[4][2], r[4];
#pragma unroll
            for (int ng = 0; ng < 2; ng++) {
                LDSM4T(r, uBg + ko + ng * 32);
                bg[2*ng][0]=r[0]; bg[2*ng][1]=r[1];
                bg[2*ng+1][0]=r[2]; bg[2*ng+1][1]=r[3];
                LDSM4T(r, uBu + ko + ng * 32);
                bu[2*ng][0]=r[0]; bu[2*ng][1]=r[1];
                bu[2*ng+1][0]=r[2]; bu[2*ng+1][1]=r[3];
            }
#pragma unroll
            for (int nt = 0; nt < 4; nt++)
#pragma unroll
                for (int mt = 0; mt < 2; mt++) {
                    MMA16816(accG[mt][nt], ah[mt], bg[nt][0], bg[nt][1]);
                    MMA16816(accG[mt][nt], al[mt], bg[nt][0], bg[nt][1]);
                    MMA16816(accU[mt][nt], ah[mt], bu[nt][0], bu[nt][1]);
                    MMA16816(accU[mt][nt], al[mt], bu[nt][0], bu[nt][1]);
                }
        }
        if (c + 1 < kchunks) CP_WAIT0();
        __syncthreads();
    }

    // ---- epilogue: act = silu(g) * u -> split fp16
#pragma unroll
    for (int mt = 0; mt < 2; mt++) {
#pragma unroll
        for (int half = 0; half < 2; half++) {
            const size_t slotrow =
                (size_t)(e * CAP + m0 + wm * 32 + mt * 16 + half * 8 + fr);
#pragma unroll
            for (int nt = 0; nt < 4; nt++) {
                const int gcol = n0 + wn * 32 + nt * 8 + fc;
                float gg0 = accG[mt][nt][half * 2 + 0];
                float gg1 = accG[mt][nt][half * 2 + 1];
                float uu0 = accU[mt][nt][half * 2 + 0];
                float uu1 = accU[mt][nt][half * 2 + 1];
                float a0 = (gg0 / (1.f + __expf(-gg0))) * uu0;
                float a1 = (gg1 / (1.f + __expf(-gg1))) * uu1;
                uint32_t hi, lo;
                split2(a0, a1, hi, lo);
                *(uint32_t*)&g_acth[slotrow * HDIM + gcol] = hi;
                *(uint32_t*)&g_actl[slotrow * HDIM + gcol] = lo;
            }
        }
    }
}

// ------- down GEMM (BN2=128) + fused scatter: out[tok] = score * ACT@Wd -----
__global__ void __launch_bounds__(256, 2) gemm_down_kernel(
        const float* __restrict__ Wd, const float* __restrict__ scores,
        float* __restrict__ out) {
    extern __shared__ char smem[];
    __shared__ int   s_tok[BM];
    __shared__ float s_scr[BM];

    const int e  = blockIdx.z;
    const int m0 = blockIdx.y * BM;
    if (m0 >= g_count[e]) return;
    const int n0 = blockIdx.x * BN2;

    const size_t abase = (size_t)(e * CAP + m0) * HDIM;
    const float* Bd = Wd + (size_t)e * HDIM * DMODEL;

    const int tid  = threadIdx.x;
    const int lane = tid & 31, warp = tid >> 5;
    const int wm = warp >> 1, wn = warp & 1;
    const int fr = lane >> 2;
    const int fc = (lane & 3) * 2;

    if (tid < BM) {
        int tok = g_token_of_slot[e * CAP + m0 + tid];
        s_tok[tid] = tok;
        s_scr[tid] = (tok >= 0) ? scores[tok] : 0.f;
    }

    const uint32_t sb = smem_u32(smem);
    const uint32_t aoff = (uint32_t)(wm * 32 + (lane & 15)) * (APAD * 2)
                        + (uint32_t)(lane >> 4) * 16;
    const uint32_t boff = (uint32_t)(lane & 15) * (BNP2 * 2)
                        + (uint32_t)(wn * 64 + (lane >> 4) * 8) * 2;

    const int ar0 = tid >> 2, ac0 = (tid & 3) * 8;
    const int ar1 = ar0 + 64;
    const int bkr = tid >> 3, bcb = (tid & 7) * 16;

    auto issueA = [&](int c, int buf) {
        const int k0 = c * BK;
        const uint32_t d0 = sb + buf * A_BUF + (uint32_t)(ar0 * APAD + ac0) * 2;
        const uint32_t d1 = sb + buf * A_BUF + (uint32_t)(ar1 * APAD + ac0) * 2;
        CP16(d0,          g_acth + abase + (size_t)ar0 * HDIM + k0 + ac0);
        CP16(d0 + OFF_AL, g_actl + abase + (size_t)ar0 * HDIM + k0 + ac0);
        CP16(d1,          g_acth + abase + (size_t)ar1 * HDIM + k0 + ac0);
        CP16(d1 + OFF_AL, g_actl + abase + (size_t)ar1 * HDIM + k0 + ac0);
        CP_COMMIT();
    };

    float4 pb[4];
    auto prefetchB = [&](int c) {
        const int k0 = c * BK;
#pragma unroll
        for (int j = 0; j < 4; j++)
            pb[j] = *(const float4*)(Bd + (size_t)(k0 + bkr) * DMODEL
                                     + n0 + bcb + j * 4);
    };
    auto storeB = [&](int buf) {
        __half* pB = (__half*)(smem + OFF_B0 + buf * B_BUF2);
#pragma unroll
        for (int j = 0; j < 4; j++) {
            *(uint2*)&pB[bkr * BNP2 + bcb + j * 4] =
                make_uint2(pack_h2(pb[j].x, pb[j].y), pack_h2(pb[j].z, pb[j].w));
        }
    };

    float acc[2][8][4];
#pragma unroll
    for (int i = 0; i < 2; i++)
#pragma unroll
        for (int j = 0; j < 8; j++)
#pragma unroll
            for (int q = 0; q < 4; q++) acc[i][j][q] = 0.f;

    const int kchunks = HDIM / BK;   // 88
    prefetchB(0);
    issueA(0, 0);
    storeB(0);
    prefetchB(1);
    CP_WAIT0();
    __syncthreads();

    for (int c = 0; c < kchunks; c++) {
        const int buf = c & 1;
        if (c + 1 < kchunks) {
            issueA(c + 1, buf ^ 1);
            storeB(buf ^ 1);
            if (c + 2 < kchunks) prefetchB(c + 2);
        }

        const uint32_t uAh = sb + buf * A_BUF + aoff;
        const uint32_t uAl = uAh + OFF_AL;
        const uint32_t uBh = sb + OFF_B0 + buf * B_BUF2 + boff;

#pragma unroll
        for (int ks = 0; ks < 2; ks++) {
            const uint32_t ko = ks * (16 * BNP2 * 2);
            uint32_t ah[2][4], al[2][4];
#pragma unroll
            for (int mt = 0; mt < 2; mt++) {
                LDSM4(ah[mt], uAh + mt * (16 * APAD * 2) + ks * 32);
                LDSM4(al[mt], uAl + mt * (16 * APAD * 2) + ks * 32);
            }
#pragma unroll
            for (int nh = 0; nh < 2; nh++) {     // two n-halves of 32
                uint32_t bh[4][2], r[4];
#pragma unroll
                for (int ng = 0; ng < 2; ng++) {
                    LDSM4T(r, uBh + ko + nh * 64 + ng * 32);
                    bh[2*ng][0]=r[0]; bh[2*ng][1]=r[1];
                    bh[2*ng+1][0]=r[2]; bh[2*ng+1][1]=r[3];
                }
#pragma unroll
                for (int nt = 0; nt < 4; nt++)
#pragma unroll
                    for (int mt = 0; mt < 2; mt++) {
                        MMA16816(acc[mt][nh * 4 + nt], ah[mt], bh[nt][0], bh[nt][1]);
                        MMA16816(acc[mt][nh * 4 + nt], al[mt], bh[nt][0], bh[nt][1]);
                    }
            }
        }
        if (c + 1 < kchunks) CP_WAIT0();
        __syncthreads();
    }

    // ---- epilogue: out[token] = score * acc (fused scatter) ----
#pragma unroll
    for (int mt = 0; mt < 2; mt++) {
#pragma unroll
        for (int half = 0; half < 2; half++) {
            const int lrow = wm * 32 + mt * 16 + half * 8 + fr;
            const int tok = s_tok[lrow];
            if (tok < 0) continue;
            const float s = s_scr[lrow];
#pragma unroll
            for (int nt = 0; nt < 8; nt++) {
                const int gcol = n0 + wn * 64 + nt * 8 + fc;
                *(float2*)&out[(size_t)tok * DMODEL + gcol] =
                    make_float2(s * acc[mt][nt][half * 2 + 0],
                                s * acc[mt][nt][half * 2 + 1]);
            }
        }
    }
}

// -----------------------------------------------------------------------------
extern "C" void kernel_launch(void* const* d_in, const int* in_sizes, int n_in,
                              void* d_out, int out_size) {
    const float* x      = (const float*)d_in[0];
    const int*   idxw   = (const int*)d_in[1];
    const float* scores = (const float*)d_in[2];
    const float* Wg     = (const float*)d_in[3];
    const float* Wu     = (const float*)d_in[4];
    const float* Wd     = (const float*)d_in[5];
    float*       out    = (float*)d_out;

    cudaFuncSetAttribute(gemm_gu_kernel,
                         cudaFuncAttributeMaxDynamicSharedMemorySize, SMEM_GU);
    cudaFuncSetAttribute(gemm_down_kernel,
                         cudaFuncAttributeMaxDynamicSharedMemorySize, SMEM_DN);

    route_kernel<<<1, 256>>>(idxw);
    gather_prefill_kernel<<<N_TOK, 256>>>(x, out);

    gemm_gu_kernel<<<dim3(HDIM / BN, CAP / BM, NEXP), 256, SMEM_GU>>>(Wg, Wu);
    gemm_down_kernel<<<dim3(DMODEL / BN2, CAP / BM, NEXP), 256, SMEM_DN>>>(
        Wd, scores, out);
}